// round 12
// baseline (speedup 1.0000x reference)
#include <cuda_runtime.h>

#define BATCH 256
#define NROWS 256
#define MCOLS 256
#define DDIM  32
#define TPB   384                 // warps 0-7: dist producers, 8-11: DP consumers
#define NBLK  128                 // column pairs
#define CITER 159                 // NBLK + 31 consumer iterations
#define RING2 34                  // dist ring depth in blocks (68 columns)
#define LOG2E 1.4426950408889634f
#define BIGF  (1e8f * LOG2E)      // boundary in scaled (D*log2e) domain

__device__ float g_part[BATCH];
__device__ int   g_count;

typedef unsigned long long u64;

#define FMA_F32X2(d, a, b) \
    asm("fma.rn.f32x2 %0, %1, %2, %0;" : "+l"(d) : "l"(a), "l"(b))
#define UNPACK_F32X2(lo, hi, in) \
    asm("mov.b64 {%0, %1}, %2;" : "=f"(lo), "=f"(hi) : "l"(in))

__device__ __forceinline__ float ex2f(float x) {
    float r; asm("ex2.approx.f32 %0, %1;" : "=f"(r) : "f"(x)); return r;
}
__device__ __forceinline__ float lg2f(float x) {
    float r; asm("lg2.approx.f32 %0, %1;" : "=f"(r) : "f"(x)); return r;
}
__device__ __forceinline__ float softmin3s(float a, float b, float c) {
    float mn = fminf(fminf(a, b), c);
    float s  = ex2f(mn - a) + ex2f(mn - b) + ex2f(mn - c);
    return mn - lg2f(s);
}

// dynamic smem layout (bytes)
#define OFF_SY    0        // ulonglong2[8][256]  y chunk-transposed        32768
#define OFF_SYN   32768    // float[256] |y_j|^2  (reused for reduction)     1024
#define OFF_RING  33792    // [4 consumers][RING2 slots][64 rows x 8B]      69632
#define OFF_PROG  103424   // int[8] producer progress + pad                  64
#define OFF_WRNG  103488   // ulonglong2[3][NBLK] dp handoff                6144
#define OFF_CONS  109632   // int[4] consumer progress + pad                  64
#define SMEM_BYTES 109696

__global__ void __launch_bounds__(TPB, 2)
sdtw_kernel(const float* __restrict__ X, const float* __restrict__ Y,
            float* __restrict__ out) {
    extern __shared__ unsigned char sm[];
    ulonglong2*    sy16 = (ulonglong2*)(sm + OFF_SY);
    float*         syn  = (float*)(sm + OFF_SYN);
    volatile int*  prog = (volatile int*)(sm + OFF_PROG);
    volatile int*  cons = (volatile int*)(sm + OFF_CONS);
    __shared__ int islast;

    const int t    = threadIdx.x;
    const int lane = t & 31;
    const int wid  = t >> 5;
    const int b    = blockIdx.x;
    const float* xb = X + (size_t)b * NROWS * DDIM;
    const float* yb = Y + (size_t)b * MCOLS * DDIM;

    // ---- stage y chunk-transposed: sy16[c2][j] = float4 #c2 of y col j ----
    const ulonglong2* yb16 = (const ulonglong2*)yb;
    for (int k = t; k < MCOLS * 8; k += TPB) {
        int j = k >> 3, c2 = k & 7;
        sy16[c2 * 256 + j] = yb16[k];
    }
    if (t < MCOLS) {   // |y_j|^2
        const float4* row = (const float4*)(yb + t * DDIM);
        float acc = 0.f;
        #pragma unroll
        for (int c = 0; c < 8; c++) {
            float4 v = row[c];
            acc += v.x * v.x + v.y * v.y + v.z * v.z + v.w * v.w;
        }
        syn[t] = acc;
    }
    for (int k = t; k < 3 * NBLK * 2; k += TPB) ((u64*)(sm + OFF_WRNG))[k] = 0ull;
    if (t < 8) ((int*)(sm + OFF_PROG))[t] = 0;
    if (t < 4) ((int*)(sm + OFF_CONS))[t] = 0;

    // producers (wid<8) pre-load their single x row, packed f32x2
    u64 ax[16];
    float xx = 0.f;
    if (wid < 8) {
        const int row = 64 * (wid >> 1) + 32 * (wid & 1) + lane;
        const ulonglong2* r0 = (const ulonglong2*)(xb + (size_t)row * DDIM);
        #pragma unroll
        for (int c2 = 0; c2 < 8; c2++) {
            ulonglong2 v0 = r0[c2];
            ax[2*c2] = v0.x; ax[2*c2+1] = v0.y;
            float a, bb;
            UNPACK_F32X2(a, bb, v0.x); xx += a*a + bb*bb;
            UNPACK_F32X2(a, bb, v0.y); xx += a*a + bb*bb;
        }
    }
    __syncthreads();

    if (wid < 8) {
        // ============ PRODUCER warp (c = wid>>1, half = wid&1): 32 rows ============
        const int c    = wid >> 1;
        const int half = wid & 1;
        unsigned rbase;   // ring byte addr of this lane's row slot 0
        {   void* gp = (void*)(sm + OFF_RING + (size_t)c * RING2 * 512
                               + (32 * half + lane) * 8);
            rbase = (unsigned)__cvta_generic_to_shared(gp); }
        unsigned paddr;
        {   void* gp = (void*)(prog + wid);
            paddr = (unsigned)__cvta_generic_to_shared(gp); }
        volatile int* myc = cons + c;
        int slot = 0;
        #pragma unroll 1
        for (int j = 0; j < NBLK; j++) {
            if (j >= RING2) {                       // backpressure: busy spin
                while (*myc < j - (RING2 - 1)) {}
            }
            const int c0 = 2 * j;
            u64 a0 = 0ull, a1 = 0ull;
            #pragma unroll
            for (int c2 = 0; c2 < 8; c2++) {
                ulonglong2 y0 = sy16[c2 * 256 + c0];      // broadcast LDS.128
                ulonglong2 y1 = sy16[c2 * 256 + c0 + 1];
                FMA_F32X2(a0, ax[2*c2],   y0.x);
                FMA_F32X2(a0, ax[2*c2+1], y0.y);
                FMA_F32X2(a1, ax[2*c2],   y1.x);
                FMA_F32X2(a1, ax[2*c2+1], y1.y);
            }
            float lo, hi, d0, d1;
            UNPACK_F32X2(lo, hi, a0); d0 = lo + hi;
            UNPACK_F32X2(lo, hi, a1); d1 = lo + hi;
            float xn = xx;
            d0 = fmaxf(fmaf(-2.f, d0, xn + syn[c0]),     0.f) * LOG2E;
            d1 = fmaxf(fmaf(-2.f, d1, xn + syn[c0 + 1]), 0.f) * LOG2E;
            unsigned a = rbase + (unsigned)(slot * 512);
            asm volatile("st.volatile.shared.v2.f32 [%0], {%1, %2};"
                         :: "r"(a), "f"(d0), "f"(d1));
            __syncwarp();
            if (lane == 0)
                asm volatile("st.volatile.shared.s32 [%0], %1;" :: "r"(paddr), "r"(j + 1));
            slot = (slot + 1 == RING2) ? 0 : slot + 1;
        }
    } else {
        // ============ CONSUMER warp c: DP rows 64c+2l, +1 (R11 body) ============
        const int c = wid - 8;
        unsigned rbase;
        {   void* gp = (void*)(sm + OFF_RING + (size_t)c * RING2 * 512 + lane * 16);
            rbase = (unsigned)__cvta_generic_to_shared(gp); }
        volatile int* p0 = prog + 2 * c;
        volatile int* p1 = prog + 2 * c + 1;
        unsigned caddr;
        {   void* gp = (void*)(cons + c);
            caddr = (unsigned)__cvta_generic_to_shared(gp); }
        u64* wrng = (u64*)(sm + OFF_WRNG);
        volatile u64* myw = wrng + (size_t)c * NBLK * 2;        // if c<3
        unsigned upbase = 0;
        if (c > 0) {
            void* gp = (void*)(wrng + (size_t)(c - 1) * NBLK * 2);
            upbase = (unsigned)__cvta_generic_to_shared(gp);
        }

        float left0 = BIGF, left1 = BIGF;
        float tl   = (c == 0 && lane == 0) ? 0.f : BIGF;
        float pv10 = BIGF, pv11 = BIGF;
        int slot = (RING2 - (lane % RING2)) % RING2;            // slot of bk=i-lane

        #pragma unroll 1
        for (int i = 0; i < CITER; i++) {
            float s10 = __shfl_up_sync(0xffffffffu, pv10, 1);
            float s11 = __shfl_up_sync(0xffffffffu, pv11, 1);

            // both producers ready (first-try hit: producers run ~3x faster)
            {
                const int need = (i + 1 < NBLK) ? i + 1 : NBLK;
                while (*p0 < need || *p1 < need) {}
            }

            // own dist tile for block bk = i - lane:
            // (row0c0, row0c1, row1c0, row1c1)
            unsigned a = rbase + (unsigned)(slot * 512);
            float dx, dy, dz, dw;
            asm volatile("ld.volatile.shared.v4.f32 {%0, %1, %2, %3}, [%4];"
                         : "=f"(dx), "=f"(dy), "=f"(dz), "=f"(dw) : "r"(a));

            // cross-warp up pair: all lanes read + uniform spin, SEL into lane 0
            float up0 = BIGF, up1 = BIGF;
            if (c > 0) {
                const int ii = (i < NBLK) ? i : (NBLK - 1);
                const unsigned tag = (unsigned)(ii + 1);
                unsigned ua = upbase + (unsigned)(ii * 16);
                u64 w0, w1;
                asm volatile("ld.volatile.shared.v2.u64 {%0, %1}, [%2];"
                             : "=l"(w0), "=l"(w1) : "r"(ua));
                while ((unsigned)(w0 >> 32) != tag || (unsigned)(w1 >> 32) != tag) {
                    asm volatile("ld.volatile.shared.v2.u64 {%0, %1}, [%2];"
                                 : "=l"(w0), "=l"(w1) : "r"(ua));
                }
                up0 = __uint_as_float((unsigned)w0);
                up1 = __uint_as_float((unsigned)w1);
            }
            up0 = (lane == 0) ? up0 : s10;
            up1 = (lane == 0) ? up1 : s11;

            // 2x2 cell tile, chain depth 3
            float v00 = dx + softmin3s(up0, left0, tl);
            float v10 = dz + softmin3s(v00, left1, left0);
            float v01 = dy + softmin3s(up1, v00,   up0);
            float v11 = dw + softmin3s(v01, v10,   v00);

            const int bk = i - lane;
            const bool act = (bk >= 0) && (bk < NBLK);
            tl    = act ? up1 : tl;
            left0 = act ? v01 : left0;
            left1 = act ? v11 : left1;
            pv10  = act ? v10 : pv10;
            pv11  = act ? v11 : pv11;

            if (lane == 31) {   // free ring slots (consumed through bk = i-31)
                asm volatile("st.volatile.shared.s32 [%0], %1;"
                             :: "r"(caddr), "r"(i - 30));
            }
            if (act && lane == 31 && c < 3) {
                u64 tagw = (u64)(unsigned)(bk + 1) << 32;
                myw[bk * 2 + 0] = tagw | (u64)__float_as_uint(v10);
                myw[bk * 2 + 1] = tagw | (u64)__float_as_uint(v11);
            }
            if (c == 3 && lane == 31 && bk == NBLK - 1)
                g_part[b] = v11;                    // scaled D[N][M]

            slot = (slot + 1 == RING2) ? 0 : slot + 1;
        }
    }

    // ---- fused grid reduction (last CTA); reuse syn[] as scratch ----
    __threadfence();
    __syncthreads();
    if (t == 0) islast = (atomicAdd(&g_count, 1) == BATCH - 1);
    __syncthreads();
    if (islast) {
        __threadfence();
        float* red = syn;
        if (t < 128) red[t] = g_part[t] + g_part[t + 128];
        __syncthreads();
        #pragma unroll
        for (int off = 64; off > 0; off >>= 1) {
            if (t < off) red[t] += red[t + off];
            __syncthreads();
        }
        if (t == 0) {
            out[0] = red[0] * (1.0f / ((float)BATCH * LOG2E));
            g_count = 0;                            // reset for next graph replay
        }
    }
}

extern "C" void kernel_launch(void* const* d_in, const int* in_sizes, int n_in,
                              void* d_out, int out_size) {
    const float* x = (const float*)d_in[0];
    const float* y = (const float*)d_in[1];
    float* out = (float*)d_out;
    cudaFuncSetAttribute(sdtw_kernel, cudaFuncAttributeMaxDynamicSharedMemorySize,
                         SMEM_BYTES);
    sdtw_kernel<<<BATCH, TPB, SMEM_BYTES>>>(x, y, out);
}